// round 2
// baseline (speedup 1.0000x reference)
#include <cuda_runtime.h>
#include <cuda_bf16.h>

#define BB 8
#define TOUT 256
#define TIN 512
#define LDIM 128
#define G4 512          // 4*L
#define QT 4            // q rows per attention block
#define KT 64           // key chunk in attention
#define KSTR 65         // padded stride for transposed keys tile
#define DOUT 256        // L + D_ATT

// ---------------- scratch (device globals; no allocation) ----------------
__device__ float g_xz[BB * TOUT * G4];      // input projection  (4 MB)
__device__ float g_keys[BB * TIN * LDIM];   // keys              (2 MB)
__device__ float g_q[BB * TOUT * LDIM];     // query projection  (1 MB)

// ---------------- math helpers ----------------
static __device__ __forceinline__ float sigmoid_acc(float x) {
    float e = __expf(-fabsf(x));
    float r = 1.0f / (1.0f + e);
    return (x >= 0.f) ? r : (1.0f - r);
}
static __device__ __forceinline__ float tanh_acc(float x) {
    float a = fabsf(x);
    float e = __expf(-2.0f * a);
    float r = (1.0f - e) / (1.0f + e);
    return (x >= 0.f) ? r : -r;
}
static __device__ __forceinline__ float tanh_fast(float x) {
    float y;
    asm("tanh.approx.f32 %0, %1;" : "=f"(y) : "f"(x));
    return y;
}

// ---------------- K1: keys = attended @ W1 + b1 ----------------
// 4 rows per block, 128 threads: r = t>>5, 4 cols per thread
__global__ void k_keys(const float* __restrict__ att, const float* __restrict__ W1,
                       const float* __restrict__ b1) {
    int r0 = blockIdx.x * 4;
    int t = threadIdx.x;
    __shared__ float a_sh[4][LDIM];
    for (int i = t; i < 4 * LDIM; i += 128)
        a_sh[i >> 7][i & 127] = att[(r0 + (i >> 7)) * LDIM + (i & 127)];
    __syncthreads();
    int r = t >> 5, jq = t & 31, j4 = jq * 4;
    const float4* W14 = (const float4*)W1;
    float4 acc = *(const float4*)&b1[j4];
    #pragma unroll 8
    for (int d = 0; d < LDIM; ++d) {
        float4 w = __ldg(&W14[d * 32 + jq]);
        float a = a_sh[r][d];
        acc.x = fmaf(a, w.x, acc.x); acc.y = fmaf(a, w.y, acc.y);
        acc.z = fmaf(a, w.z, acc.z); acc.w = fmaf(a, w.w, acc.w);
    }
    *(float4*)&g_keys[(r0 + r) * LDIM + j4] = acc;
}

// ---------------- K2: xz = inputs @ lstm_kernel + bias ----------------
// one row per block, 128 threads, 4 cols each (512 outputs)
__global__ void k_xz(const float* __restrict__ in, const float* __restrict__ Wk,
                     const float* __restrict__ bias) {
    int row = blockIdx.x;
    int t = threadIdx.x;
    __shared__ float x_sh[LDIM];
    x_sh[t] = in[row * LDIM + t];
    __syncthreads();
    int j4 = t * 4;
    const float4* Wk4 = (const float4*)Wk;
    float4 acc = *(const float4*)&bias[j4];
    #pragma unroll 8
    for (int d = 0; d < LDIM; ++d) {
        float4 w = __ldg(&Wk4[d * 128 + t]);
        float a = x_sh[d];
        acc.x = fmaf(a, w.x, acc.x); acc.y = fmaf(a, w.y, acc.y);
        acc.z = fmaf(a, w.z, acc.z); acc.w = fmaf(a, w.w, acc.w);
    }
    *(float4*)&g_xz[row * G4 + j4] = acc;
}

// ---------------- K3: sequential LSTM scan ----------------
// one block per batch element, 1024 threads.
// thread t: s = t>>7 (K-slice of 16 rows), jq = t&127 (4 output cols j4=jq*4)
__global__ __launch_bounds__(1024, 1)
void k_lstm(const float* __restrict__ Wr, float* __restrict__ out,
            float* __restrict__ hT, float* __restrict__ cT) {
    int b = blockIdx.x;
    int t = threadIdx.x;
    int s = t >> 7;
    int jq = t & 127;

    __shared__ float4 h4[32];            // h state (128 floats)
    __shared__ float4 psum4[8][128];     // partial GEMM sums (16 KB)
    __shared__ float act[G4];            // activated gates

    float c_reg = 0.f;
    if (t < LDIM) ((float*)h4)[t] = 0.f;

    const float4* wp = ((const float4*)Wr) + (16 * s) * 128 + jq;

    float xz_cur = 0.f;
    if (t < G4) xz_cur = g_xz[(b * TOUT + 0) * G4 + t];
    __syncthreads();

    for (int step = 0; step < TOUT; ++step) {
        // ---- GEMM partials: z[j4..j4+3] over k in [16s, 16s+16)
        float4 ha = h4[s * 4 + 0], hb = h4[s * 4 + 1];
        float4 hc = h4[s * 4 + 2], hd = h4[s * 4 + 3];
        float hk[16] = {ha.x,ha.y,ha.z,ha.w, hb.x,hb.y,hb.z,hb.w,
                        hc.x,hc.y,hc.z,hc.w, hd.x,hd.y,hd.z,hd.w};
        float a0 = 0.f, a1 = 0.f, a2 = 0.f, a3 = 0.f;
        #pragma unroll
        for (int k = 0; k < 16; ++k) {
            float4 w = __ldg(&wp[k * 128]);
            float h = hk[k];
            a0 = fmaf(h, w.x, a0); a1 = fmaf(h, w.y, a1);
            a2 = fmaf(h, w.z, a2); a3 = fmaf(h, w.w, a3);
        }
        psum4[s][jq] = make_float4(a0, a1, a2, a3);

        // prefetch next step's xz while GEMM results drain
        float xz_next = 0.f;
        if (t < G4 && step + 1 < TOUT)
            xz_next = g_xz[(b * TOUT + step + 1) * G4 + t];
        __syncthreads();

        // ---- combine + nonlinearity (512 threads)
        if (t < G4) {
            float z = xz_cur;
            const float* ps = (const float*)psum4;
            #pragma unroll
            for (int s2 = 0; s2 < 8; ++s2) z += ps[s2 * G4 + t];
            int quad = t >> 7;
            act[t] = (quad == 2) ? tanh_acc(z) : sigmoid_acc(z);
        }
        __syncthreads();

        // ---- gate update (128 threads)
        if (t < LDIM) {
            float ai = act[t], af = act[LDIM + t];
            float ag = act[2 * LDIM + t], ao = act[3 * LDIM + t];
            c_reg = af * c_reg + ai * ag;
            float h = ao * tanh_acc(c_reg);
            ((float*)h4)[t] = h;
            out[(b * TOUT + step) * DOUT + t] = h;   // x half of output row
        }
        xz_cur = xz_next;
        __syncthreads();
    }
    if (t < LDIM) {
        hT[b * LDIM + t] = ((float*)h4)[t];
        cT[b * LDIM + t] = c_reg;
    }
}

// ---------------- K4: q = x @ W2 + b2 (x read from out[:, :128]) ----------------
__global__ void k_q(const float* __restrict__ out, const float* __restrict__ W2,
                    const float* __restrict__ b2) {
    int r0 = blockIdx.x * 4;
    int t = threadIdx.x;
    __shared__ float x_sh[4][LDIM];
    for (int i = t; i < 4 * LDIM; i += 128)
        x_sh[i >> 7][i & 127] = out[(r0 + (i >> 7)) * DOUT + (i & 127)];
    __syncthreads();
    int r = t >> 5, jq = t & 31, j4 = jq * 4;
    const float4* W24 = (const float4*)W2;
    float4 acc = *(const float4*)&b2[j4];
    #pragma unroll 8
    for (int d = 0; d < LDIM; ++d) {
        float4 w = __ldg(&W24[d * 32 + jq]);
        float a = x_sh[r][d];
        acc.x = fmaf(a, w.x, acc.x); acc.y = fmaf(a, w.y, acc.y);
        acc.z = fmaf(a, w.z, acc.z); acc.w = fmaf(a, w.w, acc.w);
    }
    *(float4*)&g_q[(r0 + r) * LDIM + j4] = acc;
}

// ---------------- K5: scores -> softmax -> weighted sum ----------------
// grid (TOUT/QT, B), 256 threads.
__global__ __launch_bounds__(256, 2)
void k_attn(const float* __restrict__ att, const float* __restrict__ W3,
            const float* __restrict__ b3p, float* __restrict__ out) {
    __shared__ float ksh[LDIM * KSTR];   // 33280 B; score phase: keys^T; reused as att tile
    __shared__ float q_sh[QT * LDIM];
    __shared__ float sc[QT * TIN];
    __shared__ float w3_sh[LDIM];
    __shared__ float wred[8];
    __shared__ float wred2[8];

    int b = blockIdx.y;
    int q0 = blockIdx.x * QT;
    int t = threadIdx.x;

    for (int i = t; i < QT * LDIM; i += 256)
        q_sh[i] = g_q[(b * TOUT + q0 + (i >> 7)) * LDIM + (i & 127)];
    if (t < LDIM) w3_sh[t] = W3[t];
    float b3v = __ldg(b3p);

    int kl = t & 63;
    int q = t >> 6;
    int w = t >> 5, lane = t & 31;
    const float* qrow = q_sh + q * LDIM;

    // ---- scores: 8 chunks of 64 keys, keys staged transposed in smem
    for (int c = 0; c < 8; ++c) {
        __syncthreads();
        for (int i = t; i < KT * LDIM; i += 256) {
            int kk = i >> 7, l = i & 127;
            ksh[l * KSTR + kk] = g_keys[(b * TIN + c * KT + kk) * LDIM + l];
        }
        __syncthreads();
        float acc = 0.f;
        #pragma unroll 4
        for (int l = 0; l < LDIM; ++l) {
            float kv = ksh[l * KSTR + kl];
            float tv = tanh_fast(kv + qrow[l]);
            acc = fmaf(tv, w3_sh[l], acc);
        }
        sc[q * TIN + c * KT + kl] = acc + b3v;
    }
    __syncthreads();

    // ---- softmax over TIN=512 per q row (64 threads = 2 warps per row)
    float e[8];
    {
        float m = -1e30f;
        #pragma unroll
        for (int c = 0; c < 8; ++c) m = fmaxf(m, sc[q * TIN + c * KT + kl]);
        #pragma unroll
        for (int o = 16; o; o >>= 1) m = fmaxf(m, __shfl_xor_sync(0xffffffffu, m, o));
        if (lane == 0) wred[w] = m;
        __syncthreads();
        m = fmaxf(wred[q * 2], wred[q * 2 + 1]);

        float sum = 0.f;
        #pragma unroll
        for (int c = 0; c < 8; ++c) {
            e[c] = __expf(sc[q * TIN + c * KT + kl] - m);
            sum += e[c];
        }
        #pragma unroll
        for (int o = 16; o; o >>= 1) sum += __shfl_xor_sync(0xffffffffu, sum, o);
        if (lane == 0) wred2[w] = sum;
        __syncthreads();
        float inv = 1.0f / (wred2[q * 2] + wred2[q * 2 + 1]);
        #pragma unroll
        for (int c = 0; c < 8; ++c) sc[q * TIN + c * KT + kl] = e[c] * inv;
    }
    __syncthreads();

    // ---- weighted sum: out_w[q][d] = sum_k p[q][k] * att[b][k][d]
    // thread: d = t&127, qh = t>>7 handles q = qh and qh+2
    int d = t & 127;
    int qh = t >> 7;
    float acc0 = 0.f, acc1 = 0.f;
    float* ash = ksh;                    // reuse as [64][128] att tile
    for (int c = 0; c < 8; ++c) {
        __syncthreads();
        for (int i = t; i < KT * LDIM; i += 256)
            ash[i] = att[(b * TIN + c * KT + (i >> 7)) * LDIM + (i & 127)];
        __syncthreads();
        const float* p0 = sc + qh * TIN + c * KT;
        const float* p1 = sc + (qh + 2) * TIN + c * KT;
        #pragma unroll 4
        for (int k = 0; k < KT; ++k) {
            float av = ash[k * LDIM + d];
            acc0 = fmaf(p0[k], av, acc0);
            acc1 = fmaf(p1[k], av, acc1);
        }
    }
    out[(b * TOUT + q0 + qh) * DOUT + LDIM + d] = acc0;
    out[(b * TOUT + q0 + qh + 2) * DOUT + LDIM + d] = acc1;
}

// ---------------- launch ----------------
extern "C" void kernel_launch(void* const* d_in, const int* in_sizes, int n_in,
                              void* d_out, int out_size) {
    (void)in_sizes; (void)n_in; (void)out_size;
    const float* inputs   = (const float*)d_in[0];
    const float* att      = (const float*)d_in[1];
    const float* Wk       = (const float*)d_in[2];
    const float* Wr       = (const float*)d_in[3];
    const float* bias     = (const float*)d_in[4];
    const float* W1       = (const float*)d_in[5];
    const float* b1       = (const float*)d_in[6];
    const float* W2       = (const float*)d_in[7];
    const float* b2       = (const float*)d_in[8];
    const float* W3       = (const float*)d_in[9];
    const float* b3       = (const float*)d_in[10];

    float* out = (float*)d_out;                       // (B, TOUT, 256)
    float* hT  = out + BB * TOUT * DOUT;              // (B, 128)
    float* cT  = hT + BB * LDIM;                      // (B, 128)

    k_keys<<<BB * TIN / 4, 128>>>(att, W1, b1);
    k_xz<<<BB * TOUT, 128>>>(inputs, Wk, bias);
    k_lstm<<<BB, 1024>>>(Wr, out, hT, cT);
    k_q<<<BB * TOUT / 4, 128>>>(out, W2, b2);
    dim3 ag(TOUT / QT, BB);
    k_attn<<<ag, 256>>>(att, W3, b3, out);
}

// round 13
// speedup vs baseline: 1.5379x; 1.5379x over previous
#include <cuda_runtime.h>
#include <cuda_bf16.h>
#include <cstdint>

#define BB 8
#define TOUT 256
#define TIN 512
#define LDIM 128
#define G4 512          // 4*L
#define QT 4            // q rows per attention block
#define KT 64           // key chunk in attention
#define KSTR 65         // padded stride for transposed keys tile
#define DOUT 256        // L + D_ATT
#define KREG 96         // k-rows of Wr held in registers
#define KSM  32         // k-rows of Wr held in (dynamic) shared memory

// ---------------- scratch (device globals; no allocation) ----------------
__device__ float g_xz[BB * TOUT * G4];      // input projection  (4 MB)
__device__ float g_keys[BB * TIN * LDIM];   // keys              (2 MB)
__device__ float g_q[BB * TOUT * LDIM];     // query projection  (1 MB)

// ---------------- math helpers ----------------
static __device__ __forceinline__ float sigmoid_acc(float x) {
    float e = __expf(-fabsf(x));
    float r = 1.0f / (1.0f + e);
    return (x >= 0.f) ? r : (1.0f - r);
}
static __device__ __forceinline__ float tanh_acc(float x) {
    float a = fabsf(x);
    float e = __expf(-2.0f * a);
    float r = (1.0f - e) / (1.0f + e);
    return (x >= 0.f) ? r : -r;
}
static __device__ __forceinline__ float tanh_fast(float x) {
    float y;
    asm("tanh.approx.f32 %0, %1;" : "=f"(y) : "f"(x));
    return y;
}
static __device__ __forceinline__ unsigned long long pack2(float x, float y) {
    unsigned long long r;
    asm("mov.b64 %0, {%1,%2};" : "=l"(r) : "f"(x), "f"(y));
    return r;
}
static __device__ __forceinline__ unsigned long long fma2(
        unsigned long long a, unsigned long long b, unsigned long long c) {
    unsigned long long d;
    asm("fma.rn.f32x2 %0, %1, %2, %3;" : "=l"(d) : "l"(a), "l"(b), "l"(c));
    return d;
}
static __device__ __forceinline__ void unpack2(unsigned long long a, float& lo, float& hi) {
    asm("mov.b64 {%0,%1}, %2;" : "=f"(lo), "=f"(hi) : "l"(a));
}

// ---------------- K1: keys = attended @ W1 + b1 (round-2 proven) ----------------
__global__ void k_keys(const float* __restrict__ att, const float* __restrict__ W1,
                       const float* __restrict__ b1) {
    int r0 = blockIdx.x * 4;
    int t = threadIdx.x;
    __shared__ float a_sh[4][LDIM];
    for (int i = t; i < 4 * LDIM; i += 128)
        a_sh[i >> 7][i & 127] = att[(r0 + (i >> 7)) * LDIM + (i & 127)];
    __syncthreads();
    int r = t >> 5, jq = t & 31, j4 = jq * 4;
    const float4* W14 = (const float4*)W1;
    float4 acc = *(const float4*)&b1[j4];
    #pragma unroll 8
    for (int d = 0; d < LDIM; ++d) {
        float4 w = __ldg(&W14[d * 32 + jq]);
        float a = a_sh[r][d];
        acc.x = fmaf(a, w.x, acc.x); acc.y = fmaf(a, w.y, acc.y);
        acc.z = fmaf(a, w.z, acc.z); acc.w = fmaf(a, w.w, acc.w);
    }
    *(float4*)&g_keys[(r0 + r) * LDIM + j4] = acc;
}

// ---------------- K2: xz = inputs @ lstm_kernel + bias (round-2 proven) ----------------
__global__ void k_xz(const float* __restrict__ in, const float* __restrict__ Wk,
                     const float* __restrict__ bias) {
    int row = blockIdx.x;
    int t = threadIdx.x;
    __shared__ float x_sh[LDIM];
    x_sh[t] = in[row * LDIM + t];
    __syncthreads();
    int j4 = t * 4;
    const float4* Wk4 = (const float4*)Wk;
    float4 acc = *(const float4*)&bias[j4];
    #pragma unroll 8
    for (int d = 0; d < LDIM; ++d) {
        float4 w = __ldg(&Wk4[d * 128 + t]);
        float a = x_sh[d];
        acc.x = fmaf(a, w.x, acc.x); acc.y = fmaf(a, w.y, acc.y);
        acc.z = fmaf(a, w.z, acc.z); acc.w = fmaf(a, w.w, acc.w);
    }
    *(float4*)&g_xz[row * G4 + j4] = acc;
}

// ---------------- K3: LSTM scan, ONE CTA per batch, Wr in regs + dynamic smem
// 512 threads. Thread t owns gate column j = t (full k range):
//   k in [0, 96): 48 packed f32x2 weights in registers
//   k in [96,128): weights in dynamic smem w_sm[32][512] (64 KB)
// h is read with ORDINARY C++ float4 loads (ordered by __syncthreads);
// f32x2 packing happens on register values only.
__global__ __launch_bounds__(512, 1)
void k_lstm6(const float* __restrict__ Wr, float* __restrict__ out,
             float* __restrict__ hT, float* __restrict__ cT) {
    extern __shared__ float w_sm[];      // KSM * G4 floats = 64 KB (dynamic)
    __shared__ __align__(16) float h_sh[LDIM];
    __shared__ float act[G4];

    int b = blockIdx.x;
    int t = threadIdx.x;

    // stage smem weight rows (coalesced)
    for (int i = t; i < KSM * G4; i += 512)
        w_sm[i] = Wr[KREG * G4 + i];

    // register weights: k in [0,96), column t (coalesced across threads)
    unsigned long long w[48];
    #pragma unroll
    for (int kb = 0; kb < 24; ++kb) {
        float w0 = Wr[(4 * kb + 0) * G4 + t];
        float w1 = Wr[(4 * kb + 1) * G4 + t];
        float w2 = Wr[(4 * kb + 2) * G4 + t];
        float w3 = Wr[(4 * kb + 3) * G4 + t];
        w[2 * kb]     = pack2(w0, w1);
        w[2 * kb + 1] = pack2(w2, w3);
    }

    if (t < LDIM) h_sh[t] = 0.f;
    float c_reg = 0.f;
    float xz_cur = g_xz[(b * TOUT) * G4 + t];
    const float4* h4p = (const float4*)h_sh;
    __syncthreads();

    for (int step = 0; step < TOUT; ++step) {
        // ---- z_t = sum_k h[k] * Wr[k][t]  (register weights, k in [0,96))
        unsigned long long acc0 = 0ull, acc1 = 0ull;
        #pragma unroll
        for (int kb = 0; kb < 24; ++kb) {
            float4 hv = h4p[kb];                       // plain LDS.128 (sync-ordered)
            acc0 = fma2(w[2 * kb],     pack2(hv.x, hv.y), acc0);
            acc1 = fma2(w[2 * kb + 1], pack2(hv.z, hv.w), acc1);
        }
        // ---- smem weight tail: k in [96,128)
        #pragma unroll
        for (int k2 = 0; k2 < 8; ++k2) {
            float4 hv = h4p[24 + k2];
            float wa = w_sm[(k2 * 4 + 0) * G4 + t];
            float wb = w_sm[(k2 * 4 + 1) * G4 + t];
            float wc = w_sm[(k2 * 4 + 2) * G4 + t];
            float wd = w_sm[(k2 * 4 + 3) * G4 + t];
            acc0 = fma2(pack2(wa, wb), pack2(hv.x, hv.y), acc0);
            acc1 = fma2(pack2(wc, wd), pack2(hv.z, hv.w), acc1);
        }
        float lo0, hi0, lo1, hi1;
        unpack2(acc0, lo0, hi0);
        unpack2(acc1, lo1, hi1);
        float z = (lo0 + hi0) + (lo1 + hi1) + xz_cur;

        // gate activation for this column: cols [256,384) are g (tanh)
        float a = (t >= 256 && t < 384) ? tanh_acc(z) : sigmoid_acc(z);
        act[t] = a;

        // prefetch next xz while activation drains
        float xz_next = (step + 1 < TOUT) ? g_xz[(b * TOUT + step + 1) * G4 + t] : 0.f;
        __syncthreads();

        // ---- state update (128 threads)
        if (t < LDIM) {
            float gi = act[t], gf = act[LDIM + t];
            float gg = act[2 * LDIM + t], go = act[3 * LDIM + t];
            c_reg = gf * c_reg + gi * gg;
            float h = go * tanh_acc(c_reg);
            h_sh[t] = h;
            out[(b * TOUT + step) * DOUT + t] = h;
        }
        xz_cur = xz_next;
        __syncthreads();
    }
    if (t < LDIM) {
        hT[b * LDIM + t] = h_sh[t];
        cT[b * LDIM + t] = c_reg;
    }
}

// ---------------- K4: q = x @ W2 + b2 (round-2 proven) ----------------
__global__ void k_q(const float* __restrict__ out, const float* __restrict__ W2,
                    const float* __restrict__ b2) {
    int r0 = blockIdx.x * 4;
    int t = threadIdx.x;
    __shared__ float x_sh[4][LDIM];
    for (int i = t; i < 4 * LDIM; i += 128)
        x_sh[i >> 7][i & 127] = out[(r0 + (i >> 7)) * DOUT + (i & 127)];
    __syncthreads();
    int r = t >> 5, jq = t & 31, j4 = jq * 4;
    const float4* W24 = (const float4*)W2;
    float4 acc = *(const float4*)&b2[j4];
    #pragma unroll 8
    for (int d = 0; d < LDIM; ++d) {
        float4 w = __ldg(&W24[d * 32 + jq]);
        float a = x_sh[r][d];
        acc.x = fmaf(a, w.x, acc.x); acc.y = fmaf(a, w.y, acc.y);
        acc.z = fmaf(a, w.z, acc.z); acc.w = fmaf(a, w.w, acc.w);
    }
    *(float4*)&g_q[(r0 + r) * LDIM + j4] = acc;
}

// ---------------- K5: scores -> softmax -> weighted sum (round-2 proven) ----
__global__ __launch_bounds__(256, 2)
void k_attn(const float* __restrict__ att, const float* __restrict__ W3,
            const float* __restrict__ b3p, float* __restrict__ out) {
    __shared__ float ksh[LDIM * KSTR];   // score phase: keys^T; reused as att tile
    __shared__ float q_sh[QT * LDIM];
    __shared__ float sc[QT * TIN];
    __shared__ float w3_sh[LDIM];
    __shared__ float wred[8];
    __shared__ float wred2[8];

    int b = blockIdx.y;
    int q0 = blockIdx.x * QT;
    int t = threadIdx.x;

    for (int i = t; i < QT * LDIM; i += 256)
        q_sh[i] = g_q[(b * TOUT + q0 + (i >> 7)) * LDIM + (i & 127)];
    if (t < LDIM) w3_sh[t] = W3[t];
    float b3v = __ldg(b3p);

    int kl = t & 63;
    int q = t >> 6;
    int w = t >> 5, lane = t & 31;
    const float* qrow = q_sh + q * LDIM;

    // ---- scores: 8 chunks of 64 keys, keys staged transposed in smem
    for (int cc = 0; cc < 8; ++cc) {
        __syncthreads();
        for (int i = t; i < KT * LDIM; i += 256) {
            int kk = i >> 7, l = i & 127;
            ksh[l * KSTR + kk] = g_keys[(b * TIN + cc * KT + kk) * LDIM + l];
        }
        __syncthreads();
        float acc = 0.f;
        #pragma unroll 4
        for (int l = 0; l < LDIM; ++l) {
            float kv = ksh[l * KSTR + kl];
            float tv = tanh_fast(kv + qrow[l]);
            acc = fmaf(tv, w3_sh[l], acc);
        }
        sc[q * TIN + cc * KT + kl] = acc + b3v;
    }
    __syncthreads();

    // ---- softmax over TIN=512 per q row (2 warps per row)
    float e[8];
    {
        float m = -1e30f;
        #pragma unroll
        for (int cc = 0; cc < 8; ++cc) m = fmaxf(m, sc[q * TIN + cc * KT + kl]);
        #pragma unroll
        for (int o = 16; o; o >>= 1) m = fmaxf(m, __shfl_xor_sync(0xffffffffu, m, o));
        if (lane == 0) wred[w] = m;
        __syncthreads();
        m = fmaxf(wred[q * 2], wred[q * 2 + 1]);

        float sum = 0.f;
        #pragma unroll
        for (int cc = 0; cc < 8; ++cc) {
            e[cc] = __expf(sc[q * TIN + cc * KT + kl] - m);
            sum += e[cc];
        }
        #pragma unroll
        for (int o = 16; o; o >>= 1) sum += __shfl_xor_sync(0xffffffffu, sum, o);
        if (lane == 0) wred2[w] = sum;
        __syncthreads();
        float inv = 1.0f / (wred2[q * 2] + wred2[q * 2 + 1]);
        #pragma unroll
        for (int cc = 0; cc < 8; ++cc) sc[q * TIN + cc * KT + kl] = e[cc] * inv;
    }
    __syncthreads();

    // ---- weighted sum
    int d = t & 127;
    int qh = t >> 7;
    float acc0 = 0.f, acc1 = 0.f;
    float* ash = ksh;
    for (int cc = 0; cc < 8; ++cc) {
        __syncthreads();
        for (int i = t; i < KT * LDIM; i += 256)
            ash[i] = att[(b * TIN + cc * KT + (i >> 7)) * LDIM + (i & 127)];
        __syncthreads();
        const float* p0 = sc + qh * TIN + cc * KT;
        const float* p1 = sc + (qh + 2) * TIN + cc * KT;
        #pragma unroll 4
        for (int k = 0; k < KT; ++k) {
            float av = ash[k * LDIM + d];
            acc0 = fmaf(p0[k], av, acc0);
            acc1 = fmaf(p1[k], av, acc1);
        }
    }
    out[(b * TOUT + q0 + qh) * DOUT + LDIM + d] = acc0;
    out[(b * TOUT + q0 + qh + 2) * DOUT + LDIM + d] = acc1;
}

// ---------------- launch ----------------
extern "C" void kernel_launch(void* const* d_in, const int* in_sizes, int n_in,
                              void* d_out, int out_size) {
    (void)in_sizes; (void)n_in; (void)out_size;
    const float* inputs   = (const float*)d_in[0];
    const float* att      = (const float*)d_in[1];
    const float* Wk       = (const float*)d_in[2];
    const float* Wr       = (const float*)d_in[3];
    const float* bias     = (const float*)d_in[4];
    const float* W1       = (const float*)d_in[5];
    const float* b1       = (const float*)d_in[6];
    const float* W2       = (const float*)d_in[7];
    const float* b2       = (const float*)d_in[8];
    const float* W3       = (const float*)d_in[9];
    const float* b3       = (const float*)d_in[10];

    float* out = (float*)d_out;                       // (B, TOUT, 256)
    float* hT  = out + BB * TOUT * DOUT;              // (B, 128)
    float* cT  = hT + BB * LDIM;                      // (B, 128)

    // opt-in for 64 KB dynamic smem on the LSTM (idempotent, capture-safe)
    cudaFuncSetAttribute(k_lstm6, cudaFuncAttributeMaxDynamicSharedMemorySize,
                         KSM * G4 * (int)sizeof(float));

    k_keys<<<BB * TIN / 4, 128>>>(att, W1, b1);
    k_xz<<<BB * TOUT, 128>>>(inputs, Wk, bias);
    k_lstm6<<<BB, 512, KSM * G4 * sizeof(float)>>>(Wr, out, hT, cT);
    k_q<<<BB * TOUT / 4, 128>>>(out, W2, b2);
    dim3 ag(TOUT / QT, BB);
    k_attn<<<ag, 256>>>(att, W3, b3, out);
}

// round 16
// speedup vs baseline: 1.5573x; 1.0126x over previous
#include <cuda_runtime.h>
#include <cuda_bf16.h>
#include <cstdint>

#define BB 8
#define TOUT 256
#define TIN 512
#define LDIM 128
#define G4 512          // 4*L
#define QT 4            // q rows per attention block
#define KT 64           // key chunk in attention
#define KSTR 65         // padded stride for transposed keys tile
#define DOUT 256        // L + D_ATT
#define KREG 96         // k-rows of Wr held in registers

// ---------------- scratch (device globals; no allocation) ----------------
__device__ float g_xz[BB * TOUT * G4];      // input projection  (4 MB)
__device__ float g_keys[BB * TIN * LDIM];   // keys              (2 MB)
__device__ float g_q[BB * TOUT * LDIM];     // query projection  (1 MB)

// ---------------- math helpers ----------------
static __device__ __forceinline__ float sigmoid_acc(float x) {
    float e = __expf(-fabsf(x));
    float r = __fdividef(1.0f, 1.0f + e);
    return (x >= 0.f) ? r : (1.0f - r);
}
static __device__ __forceinline__ float tanh_acc(float x) {
    float a = fabsf(x);
    float e = __expf(-2.0f * a);
    float r = __fdividef(1.0f - e, 1.0f + e);
    return (x >= 0.f) ? r : -r;
}
static __device__ __forceinline__ float tanh_fast(float x) {
    float y;
    asm("tanh.approx.f32 %0, %1;" : "=f"(y) : "f"(x));
    return y;
}
static __device__ __forceinline__ unsigned long long pack2(float x, float y) {
    unsigned long long r;
    asm("mov.b64 %0, {%1,%2};" : "=l"(r) : "f"(x), "f"(y));
    return r;
}
static __device__ __forceinline__ unsigned long long fma2(
        unsigned long long a, unsigned long long b, unsigned long long c) {
    unsigned long long d;
    asm("fma.rn.f32x2 %0, %1, %2, %3;" : "=l"(d) : "l"(a), "l"(b), "l"(c));
    return d;
}
static __device__ __forceinline__ void unpack2(unsigned long long a, float& lo, float& hi) {
    asm("mov.b64 {%0,%1}, %2;" : "=f"(lo), "=f"(hi) : "l"(a));
}

// ---------------- K1/K4: 128->128 projection, 16 rows per block -------------
// DST selects the device-global destination IN DEVICE CODE (never pass a
// __device__ symbol from host code — that was the round-7..15 bug).
// DST=0 -> g_keys, DST=1 -> g_q.
template <int DST>
__global__ __launch_bounds__(256)
void k_proj128t(const float* __restrict__ src, int sstride,
                const float* __restrict__ W, const float* __restrict__ bvec) {
    float* dst = (DST == 0) ? g_keys : g_q;
    int r0 = blockIdx.x * 16;
    int t = threadIdx.x;
    __shared__ float x_sh[16][LDIM];
    for (int i = t; i < 16 * LDIM; i += 256)
        x_sh[i >> 7][i & 127] = src[(r0 + (i >> 7)) * sstride + (i & 127)];
    __syncthreads();
    int jq = t & 31, j4 = jq * 4, rg = t >> 5;   // rg 0..7 -> rows rg*2, rg*2+1
    const float4* W4 = (const float4*)W;
    float4 bb = *(const float4*)&bvec[j4];
    float4 a0 = bb, a1 = bb;
    #pragma unroll 4
    for (int d = 0; d < LDIM; ++d) {
        float4 w = __ldg(&W4[d * 32 + jq]);
        float x0 = x_sh[rg * 2][d], x1 = x_sh[rg * 2 + 1][d];
        a0.x = fmaf(x0, w.x, a0.x); a0.y = fmaf(x0, w.y, a0.y);
        a0.z = fmaf(x0, w.z, a0.z); a0.w = fmaf(x0, w.w, a0.w);
        a1.x = fmaf(x1, w.x, a1.x); a1.y = fmaf(x1, w.y, a1.y);
        a1.z = fmaf(x1, w.z, a1.z); a1.w = fmaf(x1, w.w, a1.w);
    }
    *(float4*)&dst[(r0 + rg * 2) * LDIM + j4] = a0;
    *(float4*)&dst[(r0 + rg * 2 + 1) * LDIM + j4] = a1;
}

// ---------------- K2: xz = inputs @ lstm_kernel + bias, 16 rows/block -------
// (writes g_xz directly in device code — always did, always safe)
__global__ __launch_bounds__(256)
void k_xz2(const float* __restrict__ in, const float* __restrict__ Wk,
           const float* __restrict__ bias) {
    int r0 = blockIdx.x * 16;
    int t = threadIdx.x;
    __shared__ float x_sh[16][LDIM];
    for (int i = t; i < 16 * LDIM; i += 256)
        x_sh[i >> 7][i & 127] = in[(r0 + (i >> 7)) * LDIM + (i & 127)];
    __syncthreads();
    int jc = t & 127, j4 = jc * 4, rg = t >> 7;   // rg 0..1 -> rows rg*8..rg*8+7
    const float4* Wk4 = (const float4*)Wk;
    float4 bb = *(const float4*)&bias[j4];
    float4 acc[8];
    #pragma unroll
    for (int r = 0; r < 8; ++r) acc[r] = bb;
    #pragma unroll 2
    for (int d = 0; d < LDIM; ++d) {
        float4 w = __ldg(&Wk4[d * 128 + jc]);
        #pragma unroll
        for (int r = 0; r < 8; ++r) {
            float x = x_sh[rg * 8 + r][d];
            acc[r].x = fmaf(x, w.x, acc[r].x); acc[r].y = fmaf(x, w.y, acc[r].y);
            acc[r].z = fmaf(x, w.z, acc[r].z); acc[r].w = fmaf(x, w.w, acc[r].w);
        }
    }
    #pragma unroll
    for (int r = 0; r < 8; ++r)
        *(float4*)&g_xz[(r0 + rg * 8 + r) * G4 + j4] = acc[r];
}

// ---------------- K3: LSTM scan, ONE CTA per batch, Wr in regs + dyn smem ---
// 512 threads. Thread t owns gate column j = t (full k range):
//   k in [0, 96): 48 packed f32x2 weights in registers
//   k in [96,128): pre-packed f32x2 pairs in dynamic smem w_sm2[16][512] (64 KB)
// h is read with ordinary C++ float4 loads (ordered by __syncthreads).
__global__ __launch_bounds__(512, 1)
void k_lstm8(const float* __restrict__ Wr, float* __restrict__ out,
             float* __restrict__ hT, float* __restrict__ cT) {
    extern __shared__ unsigned long long w_sm2[];   // 16 * 512 * 8B = 64 KB
    __shared__ __align__(16) float h_sh[LDIM];
    __shared__ float act[G4];

    int b = blockIdx.x;
    int t = threadIdx.x;

    // stage smem tail weights as packed (k even, k odd) pairs
    // w_sm2[p][c] = (Wr[96+2p][c], Wr[96+2p+1][c])
    for (int i = t; i < 16 * G4; i += 512) {
        int p = i >> 9, c = i & 511;
        w_sm2[p * G4 + c] = pack2(Wr[(KREG + 2 * p) * G4 + c],
                                  Wr[(KREG + 2 * p + 1) * G4 + c]);
    }

    // register weights: k in [0,96), column t (coalesced across threads)
    unsigned long long w[48];
    #pragma unroll
    for (int kb = 0; kb < 24; ++kb) {
        float w0 = Wr[(4 * kb + 0) * G4 + t];
        float w1 = Wr[(4 * kb + 1) * G4 + t];
        float w2 = Wr[(4 * kb + 2) * G4 + t];
        float w3 = Wr[(4 * kb + 3) * G4 + t];
        w[2 * kb]     = pack2(w0, w1);
        w[2 * kb + 1] = pack2(w2, w3);
    }

    if (t < LDIM) h_sh[t] = 0.f;
    float c_reg = 0.f;
    float xz_cur = g_xz[(b * TOUT) * G4 + t];
    const float4* h4p = (const float4*)h_sh;
    __syncthreads();

    for (int step = 0; step < TOUT; ++step) {
        // ---- z_t = sum_k h[k] * Wr[k][t]  (register weights, k in [0,96))
        unsigned long long acc0 = 0ull, acc1 = 0ull;
        #pragma unroll
        for (int kb = 0; kb < 24; ++kb) {
            float4 hv = h4p[kb];                       // plain LDS.128 (sync-ordered)
            acc0 = fma2(w[2 * kb],     pack2(hv.x, hv.y), acc0);
            acc1 = fma2(w[2 * kb + 1], pack2(hv.z, hv.w), acc1);
        }
        // ---- smem weight tail: k in [96,128), packed pairs (one LDS.64 each)
        #pragma unroll
        for (int k2 = 0; k2 < 8; ++k2) {
            float4 hv = h4p[24 + k2];
            unsigned long long wab = w_sm2[(2 * k2) * G4 + t];
            unsigned long long wcd = w_sm2[(2 * k2 + 1) * G4 + t];
            acc0 = fma2(wab, pack2(hv.x, hv.y), acc0);
            acc1 = fma2(wcd, pack2(hv.z, hv.w), acc1);
        }
        float lo0, hi0, lo1, hi1;
        unpack2(acc0, lo0, hi0);
        unpack2(acc1, lo1, hi1);
        float z = (lo0 + hi0) + (lo1 + hi1) + xz_cur;

        // gate activation for this column: cols [256,384) are g (tanh)
        float a = (t >= 256 && t < 384) ? tanh_acc(z) : sigmoid_acc(z);
        act[t] = a;

        // prefetch next xz while activation drains
        float xz_next = (step + 1 < TOUT) ? g_xz[(b * TOUT + step + 1) * G4 + t] : 0.f;
        __syncthreads();

        // ---- state update (128 threads)
        if (t < LDIM) {
            float gi = act[t], gf = act[LDIM + t];
            float gg = act[2 * LDIM + t], go = act[3 * LDIM + t];
            c_reg = gf * c_reg + gi * gg;
            float h = go * tanh_acc(c_reg);
            h_sh[t] = h;
            out[(b * TOUT + step) * DOUT + t] = h;
        }
        xz_cur = xz_next;
        __syncthreads();
    }
    if (t < LDIM) {
        hT[b * LDIM + t] = h_sh[t];
        cT[b * LDIM + t] = c_reg;
    }
}

// ---------------- K5: scores -> softmax -> weighted sum (proven) ------------
__global__ __launch_bounds__(256, 2)
void k_attn(const float* __restrict__ att, const float* __restrict__ W3,
            const float* __restrict__ b3p, float* __restrict__ out) {
    __shared__ float ksh[LDIM * KSTR];   // score phase: keys^T; reused as att tile
    __shared__ float q_sh[QT * LDIM];
    __shared__ float sc[QT * TIN];
    __shared__ float w3_sh[LDIM];
    __shared__ float wred[8];
    __shared__ float wred2[8];

    int b = blockIdx.y;
    int q0 = blockIdx.x * QT;
    int t = threadIdx.x;

    for (int i = t; i < QT * LDIM; i += 256)
        q_sh[i] = g_q[(b * TOUT + q0 + (i >> 7)) * LDIM + (i & 127)];
    if (t < LDIM) w3_sh[t] = W3[t];
    float b3v = __ldg(b3p);

    int kl = t & 63;
    int q = t >> 6;
    int w = t >> 5, lane = t & 31;
    const float* qrow = q_sh + q * LDIM;

    // ---- scores: 8 chunks of 64 keys, keys staged transposed in smem
    for (int cc = 0; cc < 8; ++cc) {
        __syncthreads();
        for (int i = t; i < KT * LDIM; i += 256) {
            int kk = i >> 7, l = i & 127;
            ksh[l * KSTR + kk] = g_keys[(b * TIN + cc * KT + kk) * LDIM + l];
        }
        __syncthreads();
        float acc = 0.f;
        #pragma unroll 4
        for (int l = 0; l < LDIM; ++l) {
            float kv = ksh[l * KSTR + kl];
            float tv = tanh_fast(kv + qrow[l]);
            acc = fmaf(tv, w3_sh[l], acc);
        }
        sc[q * TIN + cc * KT + kl] = acc + b3v;
    }
    __syncthreads();

    // ---- softmax over TIN=512 per q row (2 warps per row)
    float e[8];
    {
        float m = -1e30f;
        #pragma unroll
        for (int cc = 0; cc < 8; ++cc) m = fmaxf(m, sc[q * TIN + cc * KT + kl]);
        #pragma unroll
        for (int o = 16; o; o >>= 1) m = fmaxf(m, __shfl_xor_sync(0xffffffffu, m, o));
        if (lane == 0) wred[w] = m;
        __syncthreads();
        m = fmaxf(wred[q * 2], wred[q * 2 + 1]);

        float sum = 0.f;
        #pragma unroll
        for (int cc = 0; cc < 8; ++cc) {
            e[cc] = __expf(sc[q * TIN + cc * KT + kl] - m);
            sum += e[cc];
        }
        #pragma unroll
        for (int o = 16; o; o >>= 1) sum += __shfl_xor_sync(0xffffffffu, sum, o);
        if (lane == 0) wred2[w] = sum;
        __syncthreads();
        float inv = 1.0f / (wred2[q * 2] + wred2[q * 2 + 1]);
        #pragma unroll
        for (int cc = 0; cc < 8; ++cc) sc[q * TIN + cc * KT + kl] = e[cc] * inv;
    }
    __syncthreads();

    // ---- weighted sum
    int d = t & 127;
    int qh = t >> 7;
    float acc0 = 0.f, acc1 = 0.f;
    float* ash = ksh;
    for (int cc = 0; cc < 8; ++cc) {
        __syncthreads();
        for (int i = t; i < KT * LDIM; i += 256)
            ash[i] = att[(b * TIN + cc * KT + (i >> 7)) * LDIM + (i & 127)];
        __syncthreads();
        const float* p0 = sc + qh * TIN + cc * KT;
        const float* p1 = sc + (qh + 2) * TIN + cc * KT;
        #pragma unroll 4
        for (int k = 0; k < KT; ++k) {
            float av = ash[k * LDIM + d];
            acc0 = fmaf(p0[k], av, acc0);
            acc1 = fmaf(p1[k], av, acc1);
        }
    }
    out[(b * TOUT + q0 + qh) * DOUT + LDIM + d] = acc0;
    out[(b * TOUT + q0 + qh + 2) * DOUT + LDIM + d] = acc1;
}

// ---------------- launch ----------------
extern "C" void kernel_launch(void* const* d_in, const int* in_sizes, int n_in,
                              void* d_out, int out_size) {
    (void)in_sizes; (void)n_in; (void)out_size;
    const float* inputs   = (const float*)d_in[0];
    const float* att      = (const float*)d_in[1];
    const float* Wk       = (const float*)d_in[2];
    const float* Wr       = (const float*)d_in[3];
    const float* bias     = (const float*)d_in[4];
    const float* W1       = (const float*)d_in[5];
    const float* b1       = (const float*)d_in[6];
    const float* W2       = (const float*)d_in[7];
    const float* b2       = (const float*)d_in[8];
    const float* W3       = (const float*)d_in[9];
    const float* b3       = (const float*)d_in[10];

    float* out = (float*)d_out;                       // (B, TOUT, 256)
    float* hT  = out + BB * TOUT * DOUT;              // (B, 128)
    float* cT  = hT + BB * LDIM;                      // (B, 128)

    // opt-in for 64 KB dynamic smem on the LSTM (capture-safe host attribute)
    cudaFuncSetAttribute(k_lstm8, cudaFuncAttributeMaxDynamicSharedMemorySize,
                         16 * G4 * (int)sizeof(unsigned long long));

    k_proj128t<0><<<BB * TIN / 16, 256>>>(att, LDIM, W1, b1);      // -> g_keys
    k_xz2<<<BB * TOUT / 16, 256>>>(inputs, Wk, bias);
    k_lstm8<<<BB, 512, 16 * G4 * sizeof(unsigned long long)>>>(Wr, out, hT, cT);
    k_proj128t<1><<<BB * TOUT / 16, 256>>>(out, DOUT, W2, b2);     // -> g_q
    dim3 ag(TOUT / QT, BB);
    k_attn<<<ag, 256>>>(att, W3, b3, out);
}

// round 17
// speedup vs baseline: 1.6441x; 1.0557x over previous
#include <cuda_runtime.h>
#include <cuda_bf16.h>
#include <cstdint>

#define BB 8
#define TOUT 256
#define TIN 512
#define LDIM 128
#define G4 512          // 4*L
#define QT 4            // q rows per attention block
#define KT 64           // key chunk in attention
#define KSTR 65         // padded stride for transposed keys tile
#define DOUT 256        // L + D_ATT
#define KREG 96         // k-rows of Wr held in registers

// ---------------- scratch (device globals; no allocation) ----------------
__device__ float g_xz[BB * TOUT * G4];      // input projection  (4 MB)
__device__ float g_keys[BB * TIN * LDIM];   // keys              (2 MB)

// ---------------- math helpers ----------------
static __device__ __forceinline__ float sigmoid_acc(float x) {
    float e = __expf(-fabsf(x));
    float r = __fdividef(1.0f, 1.0f + e);
    return (x >= 0.f) ? r : (1.0f - r);
}
static __device__ __forceinline__ float tanh_acc(float x) {
    float a = fabsf(x);
    float e = __expf(-2.0f * a);
    float r = __fdividef(1.0f - e, 1.0f + e);
    return (x >= 0.f) ? r : -r;
}
static __device__ __forceinline__ float tanh_fast(float x) {
    float y;
    asm("tanh.approx.f32 %0, %1;" : "=f"(y) : "f"(x));
    return y;
}
static __device__ __forceinline__ unsigned long long pack2(float x, float y) {
    unsigned long long r;
    asm("mov.b64 %0, {%1,%2};" : "=l"(r) : "f"(x), "f"(y));
    return r;
}
static __device__ __forceinline__ unsigned long long fma2(
        unsigned long long a, unsigned long long b, unsigned long long c) {
    unsigned long long d;
    asm("fma.rn.f32x2 %0, %1, %2, %3;" : "=l"(d) : "l"(a), "l"(b), "l"(c));
    return d;
}
static __device__ __forceinline__ void unpack2(unsigned long long a, float& lo, float& hi) {
    asm("mov.b64 {%0,%1}, %2;" : "=f"(lo), "=f"(hi) : "l"(a));
}

// ---------------- K1: fused keys-projection + xz-projection -----------------
// blocks [0,256):   keys rows 16*blk        (g_keys = att @ W1 + b1)
// blocks [256,384): xz rows 16*(blk-256)    (g_xz   = inputs @ Wk + bias)
__global__ __launch_bounds__(256)
void k_pre(const float* __restrict__ att, const float* __restrict__ W1,
           const float* __restrict__ b1,
           const float* __restrict__ inputs, const float* __restrict__ Wk,
           const float* __restrict__ bias) {
    int t = threadIdx.x;
    __shared__ float x_sh[16][LDIM];

    if (blockIdx.x < 256) {
        // ---- keys part (16 rows per block)
        int r0 = blockIdx.x * 16;
        for (int i = t; i < 16 * LDIM; i += 256)
            x_sh[i >> 7][i & 127] = att[(r0 + (i >> 7)) * LDIM + (i & 127)];
        __syncthreads();
        int jq = t & 31, j4 = jq * 4, rg = t >> 5;
        const float4* W4 = (const float4*)W1;
        float4 bb = *(const float4*)&b1[j4];
        float4 a0 = bb, a1 = bb;
        #pragma unroll 4
        for (int d = 0; d < LDIM; ++d) {
            float4 w = __ldg(&W4[d * 32 + jq]);
            float x0 = x_sh[rg * 2][d], x1 = x_sh[rg * 2 + 1][d];
            a0.x = fmaf(x0, w.x, a0.x); a0.y = fmaf(x0, w.y, a0.y);
            a0.z = fmaf(x0, w.z, a0.z); a0.w = fmaf(x0, w.w, a0.w);
            a1.x = fmaf(x1, w.x, a1.x); a1.y = fmaf(x1, w.y, a1.y);
            a1.z = fmaf(x1, w.z, a1.z); a1.w = fmaf(x1, w.w, a1.w);
        }
        *(float4*)&g_keys[(r0 + rg * 2) * LDIM + j4] = a0;
        *(float4*)&g_keys[(r0 + rg * 2 + 1) * LDIM + j4] = a1;
    } else {
        // ---- xz part (16 rows per block)
        int r0 = (blockIdx.x - 256) * 16;
        for (int i = t; i < 16 * LDIM; i += 256)
            x_sh[i >> 7][i & 127] = inputs[(r0 + (i >> 7)) * LDIM + (i & 127)];
        __syncthreads();
        int jc = t & 127, j4 = jc * 4, rg = t >> 7;
        const float4* Wk4 = (const float4*)Wk;
        float4 bb = *(const float4*)&bias[j4];
        float4 acc[8];
        #pragma unroll
        for (int r = 0; r < 8; ++r) acc[r] = bb;
        #pragma unroll 2
        for (int d = 0; d < LDIM; ++d) {
            float4 w = __ldg(&Wk4[d * 128 + jc]);
            #pragma unroll
            for (int r = 0; r < 8; ++r) {
                float x = x_sh[rg * 8 + r][d];
                acc[r].x = fmaf(x, w.x, acc[r].x); acc[r].y = fmaf(x, w.y, acc[r].y);
                acc[r].z = fmaf(x, w.z, acc[r].z); acc[r].w = fmaf(x, w.w, acc[r].w);
            }
        }
        #pragma unroll
        for (int r = 0; r < 8; ++r)
            *(float4*)&g_xz[(r0 + rg * 8 + r) * G4 + j4] = acc[r];
    }
}

// ---------------- K2: LSTM scan, ONE CTA per batch, Wr in regs + dyn smem ---
// 512 threads. Thread t owns gate column j = t (full k range):
//   k in [0, 96): 48 packed f32x2 weights in registers
//   k in [96,128): pre-packed f32x2 pairs in dynamic smem w_sm2[16][512] (64 KB)
// h read as ulonglong2 (LDS.128 -> two u64 regs, no pack MOVs; sync-ordered).
__global__ __launch_bounds__(512, 1)
void k_lstm9(const float* __restrict__ Wr, float* __restrict__ out,
             float* __restrict__ hT, float* __restrict__ cT) {
    extern __shared__ unsigned long long w_sm2[];   // 16 * 512 * 8B = 64 KB
    __shared__ __align__(16) float h_sh[LDIM];
    __shared__ float act[G4];

    int b = blockIdx.x;
    int t = threadIdx.x;

    // stage smem tail weights as packed (k even, k odd) pairs
    for (int i = t; i < 16 * G4; i += 512) {
        int p = i >> 9, c = i & 511;
        w_sm2[p * G4 + c] = pack2(Wr[(KREG + 2 * p) * G4 + c],
                                  Wr[(KREG + 2 * p + 1) * G4 + c]);
    }

    // register weights: k in [0,96), column t (coalesced across threads)
    unsigned long long w[48];
    #pragma unroll
    for (int kb = 0; kb < 24; ++kb) {
        float w0 = Wr[(4 * kb + 0) * G4 + t];
        float w1 = Wr[(4 * kb + 1) * G4 + t];
        float w2 = Wr[(4 * kb + 2) * G4 + t];
        float w3 = Wr[(4 * kb + 3) * G4 + t];
        w[2 * kb]     = pack2(w0, w1);
        w[2 * kb + 1] = pack2(w2, w3);
    }

    if (t < LDIM) h_sh[t] = 0.f;
    float c_reg = 0.f;
    float xz_cur = g_xz[(b * TOUT) * G4 + t];
    const ulonglong2* h2p = (const ulonglong2*)h_sh;   // (h[4k],h[4k+1]),(h[4k+2],h[4k+3])
    __syncthreads();

    for (int step = 0; step < TOUT; ++step) {
        // ---- z_t = sum_k h[k] * Wr[k][t]  (register weights, k in [0,96))
        unsigned long long acc0 = 0ull, acc1 = 0ull;
        #pragma unroll
        for (int kb = 0; kb < 24; ++kb) {
            ulonglong2 hv = h2p[kb];                   // LDS.128, two packed f32x2
            acc0 = fma2(w[2 * kb],     hv.x, acc0);
            acc1 = fma2(w[2 * kb + 1], hv.y, acc1);
        }
        // ---- smem weight tail: k in [96,128), packed pairs (one LDS.64 each)
        #pragma unroll
        for (int k2 = 0; k2 < 8; ++k2) {
            ulonglong2 hv = h2p[24 + k2];
            unsigned long long wab = w_sm2[(2 * k2) * G4 + t];
            unsigned long long wcd = w_sm2[(2 * k2 + 1) * G4 + t];
            acc0 = fma2(wab, hv.x, acc0);
            acc1 = fma2(wcd, hv.y, acc1);
        }
        float lo0, hi0, lo1, hi1;
        unpack2(acc0, lo0, hi0);
        unpack2(acc1, lo1, hi1);
        float z = (lo0 + hi0) + (lo1 + hi1) + xz_cur;

        // gate activation for this column: cols [256,384) are g (tanh)
        float a = (t >= 256 && t < 384) ? tanh_acc(z) : sigmoid_acc(z);
        act[t] = a;

        // prefetch next xz while activation drains
        float xz_next = (step + 1 < TOUT) ? g_xz[(b * TOUT + step + 1) * G4 + t] : 0.f;
        __syncthreads();

        // ---- state update (128 threads)
        if (t < LDIM) {
            float gi = act[t], gf = act[LDIM + t];
            float gg = act[2 * LDIM + t], go = act[3 * LDIM + t];
            c_reg = gf * c_reg + gi * gg;
            float h = go * tanh_acc(c_reg);
            h_sh[t] = h;
            out[(b * TOUT + step) * DOUT + t] = h;
        }
        xz_cur = xz_next;
        __syncthreads();
    }
    if (t < LDIM) {
        hT[b * LDIM + t] = h_sh[t];
        cT[b * LDIM + t] = c_reg;
    }
}

// ---------------- K3: fused q-projection + scores + softmax + weighted sum --
__global__ __launch_bounds__(256, 2)
void k_attn2(const float* __restrict__ att, const float* __restrict__ W2,
             const float* __restrict__ b2, const float* __restrict__ W3,
             const float* __restrict__ b3p, float* __restrict__ out) {
    __shared__ float ksh[LDIM * KSTR];   // score phase: keys^T; reused as att tile
    __shared__ float q_sh[QT * LDIM];
    __shared__ float x_sh[QT * LDIM];
    __shared__ float sc[QT * TIN];
    __shared__ float w3_sh[LDIM];
    __shared__ float wred[8];
    __shared__ float wred2[8];

    int b = blockIdx.y;
    int q0 = blockIdx.x * QT;
    int t = threadIdx.x;

    // ---- inline q = x @ W2 + b2 for this CTA's 4 rows (x = out[:, :128])
    for (int i = t; i < QT * LDIM; i += 256)
        x_sh[i] = out[(b * TOUT + q0 + (i >> 7)) * DOUT + (i & 127)];
    if (t < LDIM) w3_sh[t] = W3[t];
    float b3v = __ldg(b3p);
    __syncthreads();
    {
        int r = t >> 7, c = t & 127;          // 2 outputs/thread: rows r, r+2
        const float* x0 = x_sh + r * LDIM;
        const float* x1 = x_sh + (r + 2) * LDIM;
        float a0a = 0.f, a0b = 0.f, a1a = 0.f, a1b = 0.f;   // split-d ILP
        #pragma unroll 4
        for (int d = 0; d < 64; ++d) {
            float wv0 = __ldg(&W2[d * LDIM + c]);
            float wv1 = __ldg(&W2[(d + 64) * LDIM + c]);
            a0a = fmaf(x0[d], wv0, a0a); a0b = fmaf(x0[d + 64], wv1, a0b);
            a1a = fmaf(x1[d], wv0, a1a); a1b = fmaf(x1[d + 64], wv1, a1b);
        }
        float bv = __ldg(&b2[c]);
        q_sh[r * LDIM + c] = a0a + a0b + bv;
        q_sh[(r + 2) * LDIM + c] = a1a + a1b + bv;
    }

    int kl = t & 63;
    int q = t >> 6;
    int w = t >> 5, lane = t & 31;
    const float* qrow = q_sh + q * LDIM;

    // ---- scores: 8 chunks of 64 keys, keys staged transposed in smem
    for (int cc = 0; cc < 8; ++cc) {
        __syncthreads();
        for (int i = t; i < KT * LDIM; i += 256) {
            int kk = i >> 7, l = i & 127;
            ksh[l * KSTR + kk] = g_keys[(b * TIN + cc * KT + kk) * LDIM + l];
        }
        __syncthreads();
        float acc = 0.f;
        #pragma unroll 4
        for (int l = 0; l < LDIM; ++l) {
            float kv = ksh[l * KSTR + kl];
            float tv = tanh_fast(kv + qrow[l]);
            acc = fmaf(tv, w3_sh[l], acc);
        }
        sc[q * TIN + cc * KT + kl] = acc + b3v;
    }
    __syncthreads();

    // ---- softmax over TIN=512 per q row (2 warps per row)
    float e[8];
    {
        float m = -1e30f;
        #pragma unroll
        for (int cc = 0; cc < 8; ++cc) m = fmaxf(m, sc[q * TIN + cc * KT + kl]);
        #pragma unroll
        for (int o = 16; o; o >>= 1) m = fmaxf(m, __shfl_xor_sync(0xffffffffu, m, o));
        if (lane == 0) wred[w] = m;
        __syncthreads();
        m = fmaxf(wred[q * 2], wred[q * 2 + 1]);

        float sum = 0.f;
        #pragma unroll
        for (int cc = 0; cc < 8; ++cc) {
            e[cc] = __expf(sc[q * TIN + cc * KT + kl] - m);
            sum += e[cc];
        }
        #pragma unroll
        for (int o = 16; o; o >>= 1) sum += __shfl_xor_sync(0xffffffffu, sum, o);
        if (lane == 0) wred2[w] = sum;
        __syncthreads();
        float inv = 1.0f / (wred2[q * 2] + wred2[q * 2 + 1]);
        #pragma unroll
        for (int cc = 0; cc < 8; ++cc) sc[q * TIN + cc * KT + kl] = e[cc] * inv;
    }
    __syncthreads();

    // ---- weighted sum
    int d = t & 127;
    int qh = t >> 7;
    float acc0 = 0.f, acc1 = 0.f;
    float* ash = ksh;
    for (int cc = 0; cc < 8; ++cc) {
        __syncthreads();
        for (int i = t; i < KT * LDIM; i += 256)
            ash[i] = att[(b * TIN + cc * KT + (i >> 7)) * LDIM + (i & 127)];
        __syncthreads();
        const float* p0 = sc + qh * TIN + cc * KT;
        const float* p1 = sc + (qh + 2) * TIN + cc * KT;
        #pragma unroll 4
        for (int k = 0; k < KT; ++k) {
            float av = ash[k * LDIM + d];
            acc0 = fmaf(p0[k], av, acc0);
            acc1 = fmaf(p1[k], av, acc1);
        }
    }
    out[(b * TOUT + q0 + qh) * DOUT + LDIM + d] = acc0;
    out[(b * TOUT + q0 + qh + 2) * DOUT + LDIM + d] = acc1;
}

// ---------------- launch ----------------
extern "C" void kernel_launch(void* const* d_in, const int* in_sizes, int n_in,
                              void* d_out, int out_size) {
    (void)in_sizes; (void)n_in; (void)out_size;
    const float* inputs   = (const float*)d_in[0];
    const float* att      = (const float*)d_in[1];
    const float* Wk       = (const float*)d_in[2];
    const float* Wr       = (const float*)d_in[3];
    const float* bias     = (const float*)d_in[4];
    const float* W1       = (const float*)d_in[5];
    const float* b1       = (const float*)d_in[6];
    const float* W2       = (const float*)d_in[7];
    const float* b2       = (const float*)d_in[8];
    const float* W3       = (const float*)d_in[9];
    const float* b3       = (const float*)d_in[10];

    float* out = (float*)d_out;                       // (B, TOUT, 256)
    float* hT  = out + BB * TOUT * DOUT;              // (B, 128)
    float* cT  = hT + BB * LDIM;                      // (B, 128)

    // opt-in for 64 KB dynamic smem on the LSTM (capture-safe host attribute)
    cudaFuncSetAttribute(k_lstm9, cudaFuncAttributeMaxDynamicSharedMemorySize,
                         16 * G4 * (int)sizeof(unsigned long long));

    k_pre<<<384, 256>>>(att, W1, b1, inputs, Wk, bias);
    k_lstm9<<<BB, 512, 16 * G4 * sizeof(unsigned long long)>>>(Wr, out, hT, cT);
    dim3 ag(TOUT / QT, BB);
    k_attn2<<<ag, 256>>>(att, W2, b2, W3, b3, out);
}